// round 14
// baseline (speedup 1.0000x reference)
#include <cuda_runtime.h>
#include <cuda_fp16.h>
#include <cstdint>

#define BB   8
#define NN   2048
#define DIN_ 256
#define DM_  256
#define NH_  4
#define DK_  64
#define ROWS (BB*NN)
#define NTILES 512
#define PERSIST 296

// ---------------- scratch (no allocations allowed) ----------------
__device__ __half g_qb[BB*NH_*NN*DK_];   // pre-scaled by scale*log2(e)
__device__ __half g_kb[BB*NH_*NN*DK_];
__device__ __half g_vb[BB*NH_*NN*DK_];
__device__ __half g_xb[ROWS*DIN_];       // x in fp16
__device__ __half g_wt[4*DM_*DIN_];      // W^T [z][n][k], fp16 (q,k,v,o)
__device__ __half g_att[ROWS*DM_];       // fp16 [b*n][h*64+d]
__device__ float g_vpart[BB*NH_*8*DK_];
__device__ int   g_start[BB];
__device__ int   g_end[BB];              // exclusive bound = last-true index
__device__ int   g_work;                 // persistent-CTA work counter
__device__ short g_order[NTILES];        // LPT tile order

#define SCL2E 0.18033688f   /* 0.125 * log2(e) */

// ---------------- small asm helpers ----------------
__device__ __forceinline__ uint32_t smem_u32(const void* p) {
    uint32_t a;
    asm("{ .reg .u64 t; cvta.to.shared.u64 t, %1; cvt.u32.u64 %0, t; }" : "=r"(a) : "l"(p));
    return a;
}
__device__ __forceinline__ uint32_t ex2_h2(uint32_t s) {
    uint32_t y; asm("ex2.approx.f16x2 %0, %1;" : "=r"(y) : "r"(s)); return y;
}
#define LDSM_X4(r0,r1,r2,r3,addr) \
    asm volatile("ldmatrix.sync.aligned.m8n8.x4.shared.b16 {%0,%1,%2,%3}, [%4];" \
        : "=r"(r0), "=r"(r1), "=r"(r2), "=r"(r3) : "r"(addr))
#define LDSM_X4_T(r0,r1,r2,r3,addr) \
    asm volatile("ldmatrix.sync.aligned.m8n8.x4.trans.shared.b16 {%0,%1,%2,%3}, [%4];" \
        : "=r"(r0), "=r"(r1), "=r"(r2), "=r"(r3) : "r"(addr))
#define MMA16816(c0,c1,c2,c3,a0,a1,a2,a3,b0,b1) \
    asm volatile("mma.sync.aligned.m16n8k16.row.col.f32.f16.f16.f32 " \
        "{%0,%1,%2,%3}, {%4,%5,%6,%7}, {%8,%9}, {%0,%1,%2,%3};" \
        : "+f"(c0), "+f"(c1), "+f"(c2), "+f"(c3) \
        : "r"(a0), "r"(a1), "r"(a2), "r"(a3), "r"(b0), "r"(b1))
#define CP_ASYNC16(smem, gptr) \
    asm volatile("cp.async.cg.shared.global [%0], [%1], 16;" :: "r"(smem), "l"(gptr))
#define CP_COMMIT() asm volatile("cp.async.commit_group;" ::: "memory")
#define CP_WAIT(n)  asm volatile("cp.async.wait_group %0;" :: "n"(n) : "memory")

// ---------------- prep: W^T cvt (z<4) + mask scan (z==4) + x cvt (z==5) ----------------
__global__ void prep_kernel(const float* __restrict__ Wq, const float* __restrict__ Wk,
                            const float* __restrict__ Wv, const float* __restrict__ Wo,
                            const int* __restrict__ mask, const float* __restrict__ x) {
    const int z = blockIdx.z;
    const int tid = threadIdx.y * 32 + threadIdx.x;
    if (z == 5) {            // x fp32 -> fp16
        int bid = blockIdx.y * 32 + blockIdx.x;
        const float4* xs = (const float4*)x;
        uint2* xd = (uint2*)g_xb;
        #pragma unroll
        for (int u = 0; u < 16; u++) {
            int idx = bid*4096 + u*256 + tid;
            float4 a = xs[idx];
            __half2 h0 = __float22half2_rn(make_float2(a.x, a.y));
            __half2 h1 = __float22half2_rn(make_float2(a.z, a.w));
            xd[idx] = make_uint2(*(uint32_t*)&h0, *(uint32_t*)&h1);
        }
        return;
    }
    if (z == 4) {            // mask scan (+ work-counter reset)
        if (blockIdx.y != 0 || blockIdx.x >= BB) return;
        int b = blockIdx.x;
        if (b == 0 && tid == 0) g_work = 0;
        __shared__ int smin, smax;
        if (tid == 0) { smin = NN; smax = -1; }
        __syncthreads();
        int lmin = NN, lmax = -1;
        for (int i = tid; i < NN; i += 256) {
            if (mask[b*NN + i]) { lmin = min(lmin, i); lmax = max(lmax, i); }
        }
        atomicMin(&smin, lmin);
        atomicMax(&smax, lmax);
        __syncthreads();
        if (tid == 0) { g_start[b] = smin; g_end[b] = smax; }
        return;
    }
    if (blockIdx.x >= 8) return;
    __shared__ float t[32][33];
    const float* W = z == 0 ? Wq : z == 1 ? Wk : z == 2 ? Wv : Wo;
    __half* wt = g_wt + (size_t)z * (DM_*DIN_);
    int n0 = blockIdx.x * 32, k0 = blockIdx.y * 32;
    for (int i = threadIdx.y; i < 32; i += 8)
        t[i][threadIdx.x] = W[(size_t)(k0 + i)*DM_ + n0 + threadIdx.x];
    __syncthreads();
    for (int i = threadIdx.y; i < 32; i += 8)
        wt[(size_t)(n0 + i)*DIN_ + k0 + threadIdx.x] = __float2half_rn(t[threadIdx.x][i]);
}

// ---------------- fused QKV GEMM, fp16 HMMA, full cp.async, 3-stage B ----------------
#define GST 72
#define GTB ((uint32_t)(64*GST*2))

__device__ __forceinline__ void gemm_prefetch_b(uint32_t dstb, const __half* wp, int tid) {
    #pragma unroll
    for (int u = 0; u < 4; u++) {
        int i = tid + u*128;
        int r = i >> 3, j = i & 7;
        CP_ASYNC16(dstb + (uint32_t)((r*GST + j*8)*2), wp + (size_t)r*DIN_ + j*8);
    }
}

__global__ void __launch_bounds__(128) qkv_hmma_kernel(const float* __restrict__ bq,
                                                       const float* __restrict__ bk,
                                                       const float* __restrict__ bv)
{
    extern __shared__ __align__(16) unsigned char dynsm[];
    const uint32_t sab = smem_u32(dynsm);
    const uint32_t sbb = sab + 4*GTB;

    const int tid = threadIdx.x, lane = tid & 31, warp = tid >> 5;
    const int m0 = blockIdx.y * 64;
    const int h  = blockIdx.x;

    {
        const __half* xp = g_xb + (size_t)m0*DIN_;
        #pragma unroll
        for (int u = 0; u < 16; u++) {
            int i = tid + u*128;
            int r = i >> 5, j8 = i & 31;
            int t = j8 >> 3, jj = j8 & 7;
            CP_ASYNC16(sab + (uint32_t)(t*GTB) + (uint32_t)((r*GST + jj*8)*2),
                       xp + (size_t)r*DIN_ + j8*8);
        }
        CP_COMMIT();
    }
    gemm_prefetch_b(sbb, g_wt + (size_t)(h*64)*DIN_, tid);
    CP_COMMIT();
    gemm_prefetch_b(sbb + GTB, g_wt + (size_t)(h*64)*DIN_ + 64, tid);
    CP_COMMIT();

    const uint32_t afo = (uint32_t)(((warp*16 + (lane & 15))*GST + (lane >> 4)*8) * 2);
    const uint32_t bfo = (uint32_t)(((((lane & 7) + ((lane >> 4) << 3))*GST) + ((lane >> 3) & 1)*8) * 2);

    float acc[32];
    #pragma unroll
    for (int i = 0; i < 32; i++) acc[i] = 0.f;

    for (int t = 0; t < 12; t++) {
        const int z = t >> 2, k0 = t & 3;
        CP_WAIT(1);
        __syncthreads();
        {
            int tn = t + 2;
            if (tn < 12) {
                int zn = tn >> 2, kn = tn & 3;
                int stn = tn % 3;
                gemm_prefetch_b(sbb + (uint32_t)(stn*GTB),
                                g_wt + (size_t)zn*(DM_*DIN_) + (size_t)(h*64)*DIN_ + kn*64, tid);
            }
            CP_COMMIT();
        }

        uint32_t af[4][4];
        const uint32_t afb = sab + (uint32_t)(k0*GTB) + afo;
        #pragma unroll
        for (int ks = 0; ks < 4; ks++)
            LDSM_X4(af[ks][0], af[ks][1], af[ks][2], af[ks][3], afb + ks*32);

        const uint32_t bfb = sbb + (uint32_t)((t % 3)*GTB) + bfo;
        #pragma unroll
        for (int ks = 0; ks < 4; ks++) {
            #pragma unroll
            for (int ntp = 0; ntp < 4; ntp++) {
                uint32_t b0, b1, b2, b3;
                LDSM_X4(b0, b1, b2, b3, bfb + (uint32_t)((ntp*16*GST + ks*16) * 2));
                MMA16816(acc[(2*ntp)*4+0], acc[(2*ntp)*4+1], acc[(2*ntp)*4+2], acc[(2*ntp)*4+3],
                         af[ks][0], af[ks][1], af[ks][2], af[ks][3], b0, b1);
                MMA16816(acc[(2*ntp+1)*4+0], acc[(2*ntp+1)*4+1], acc[(2*ntp+1)*4+2], acc[(2*ntp+1)*4+3],
                         af[ks][0], af[ks][1], af[ks][2], af[ks][3], b2, b3);
            }
        }

        if (k0 == 3) {
            const float* bias = z == 0 ? bq : z == 1 ? bk : bv;
            __half* dst = z == 0 ? g_qb : z == 1 ? g_kb : g_vb;
            const float os = z == 0 ? SCL2E : 1.f;
            const int r_lo = m0 + warp*16 + (lane >> 2);
            const int r_hi = r_lo + 8;
            const int b_lo = r_lo >> 11, n_lo = r_lo & (NN - 1);
            const int b_hi = r_hi >> 11, n_hi = r_hi & (NN - 1);
            __half* p_lo = dst + ((((size_t)b_lo*NH_ + h)*NN) + n_lo)*DK_;
            __half* p_hi = dst + ((((size_t)b_hi*NH_ + h)*NN) + n_hi)*DK_;
            #pragma unroll
            for (int j = 0; j < 8; j++) {
                int d = j*8 + (lane & 3)*2;
                float2 bv2 = *(const float2*)&bias[h*64 + d];
                __half2 lo = __float22half2_rn(make_float2((acc[4*j+0] + bv2.x)*os,
                                                           (acc[4*j+1] + bv2.y)*os));
                __half2 hi = __float22half2_rn(make_float2((acc[4*j+2] + bv2.x)*os,
                                                           (acc[4*j+3] + bv2.y)*os));
                *(uint32_t*)&p_lo[d] = *(uint32_t*)&lo;
                *(uint32_t*)&p_hi[d] = *(uint32_t*)&hi;
            }
            #pragma unroll
            for (int i = 0; i < 32; i++) acc[i] = 0.f;
        }
    }
}

// ---------------- vmean partials + tile-order sorter ----------------
__global__ void vmean_part_kernel() {      // grid (33, 8), block 256
    if (blockIdx.x == 32) {                // LPT sorter (one thread)
        if (blockIdx.y == 0 && threadIdx.x == 0) {
            int lens[BB], ord[BB];
            for (int b = 0; b < BB; b++) {
                lens[b] = g_end[b] - (g_start[b] & ~63);
                ord[b] = b;
            }
            for (int i = 0; i < BB; i++)
                for (int j = i + 1; j < BB; j++)
                    if (lens[ord[j]] > lens[ord[i]]) { int t = ord[i]; ord[i] = ord[j]; ord[j] = t; }
            int p = 0;
            for (int r = 0; r < BB; r++)
                for (int h = 0; h < NH_; h++)
                    for (int qt = 0; qt < 16; qt++)
                        g_order[p++] = (short)((((ord[r]*NH_ + h) << 4)) | qt);
        }
        return;
    }
    __shared__ float2 red[256];
    int bh = blockIdx.x, seg = blockIdx.y;
    int p = threadIdx.x & 31, grp = threadIdx.x >> 5;
    const __half* vptr = g_vb + ((size_t)bh*NN + seg*256 + grp*32)*DK_;
    float2 s = make_float2(0.f, 0.f);
    #pragma unroll 8
    for (int r = 0; r < 32; r++) {
        __half2 v = *(const __half2*)&vptr[(size_t)r*DK_ + p*2];
        float2 f = __half22float2(v);
        s.x += f.x; s.y += f.y;
    }
    red[threadIdx.x] = s;
    __syncthreads();
    if (grp == 0) {
        float2 acc = red[p];
        #pragma unroll
        for (int g = 1; g < 8; g++) {
            float2 r2 = red[p + 32*g];
            acc.x += r2.x; acc.y += r2.y;
        }
        *(float2*)&g_vpart[((size_t)bh*8 + seg)*DK_ + p*2] = acc;
    }
}

// ---------------- HMMA fp16 flash attention: persistent, LPT, softmax/PV interleaved ----------------
#define KST 72
#define QB  ((uint32_t)(128*KST*2))
#define KVB ((uint32_t)(64*KST*2))

__device__ __forceinline__ void attn_prefetch(uint32_t skb, uint32_t svb,
                                              const __half* kp, const __half* vp,
                                              int kb, int tid) {
    #pragma unroll
    for (int u = 0; u < 2; u++) {
        int i = tid + u*256;
        int r = i >> 3, j = i & 7;
        int gr = kb + r; if (gr > NN - 1) gr = NN - 1;
        uint32_t so = (uint32_t)((r*KST + j*8) * 2);
        CP_ASYNC16(skb + so, kp + (size_t)gr*DK_ + j*8);
        CP_ASYNC16(svb + so, vp + (size_t)gr*DK_ + j*8);
    }
}

__global__ void __launch_bounds__(256) attn_mma_kernel() {
    extern __shared__ __align__(16) unsigned char dynsm[];
    __shared__ float vmS[64];
    __shared__ int sIdx;
    __half* sQ = (__half*)dynsm;
    const uint32_t smb = smem_u32(dynsm);
    const uint32_t skb0 = smb + QB;
    const uint32_t svb0 = smb + QB + 3*KVB;

    const int tid = threadIdx.x, lane = tid & 31, warp = tid >> 5;
    const uint32_t kfo = (uint32_t)(((((lane & 7) + ((lane >> 4) << 3))*KST) + ((lane >> 3) & 1)*8) * 2);
    const uint32_t vfo = (uint32_t)(((((lane & 7) + (((lane >> 3) & 1) << 3))*KST) + (lane >> 4)*8) * 2);

    for (;;) {
        if (tid == 0) sIdx = atomicAdd(&g_work, 1);
        __syncthreads();               // broadcast idx; fences smem reuse from prev tile
        const int idx = sIdx;
        if (idx >= NTILES) break;
        const int tile = g_order[idx];
        const int qt = tile & 15, bh = tile >> 4;
        const int b = bh >> 2, h = bh & 3;
        const int q0 = qt * 128;
        const int kstart = g_start[b], kend = g_end[b];
        __half* outbase = g_att + ((size_t)b*NN + q0)*DM_ + h*DK_;

        if (tid < 64) {
            float s = 0.f;
            #pragma unroll
            for (int seg = 0; seg < 8; seg++)
                s += g_vpart[((size_t)bh*8 + seg)*DK_ + tid];
            vmS[tid] = s * (1.f/NN);
        }
        __syncthreads();

        const bool any = (q0 < kend) && (q0 + 127 >= kstart);
        if (!any) {
            int r = tid >> 1, c0 = (tid & 1) * 32;
            #pragma unroll
            for (int j = 0; j < 8; j++) {
                __half2 a = __float22half2_rn(make_float2(vmS[c0+j*4],   vmS[c0+j*4+1]));
                __half2 c = __float22half2_rn(make_float2(vmS[c0+j*4+2], vmS[c0+j*4+3]));
                *(uint2*)&outbase[(size_t)r*DM_ + c0 + j*4] =
                    make_uint2(*(uint32_t*)&a, *(uint32_t*)&c);
            }
            continue;
        }

        const __half* qp = g_qb + ((size_t)bh*NN + q0)*DK_;
        const __half* kp = g_kb + (size_t)bh*NN*DK_;
        const __half* vp = g_vb + (size_t)bh*NN*DK_;
        const int kb0 = kstart & ~63;

        attn_prefetch(skb0, svb0, kp, vp, kb0, tid);
        CP_COMMIT();
        if (kb0 + 64 < kend)
            attn_prefetch(skb0 + KVB, svb0 + KVB, kp, vp, kb0 + 64, tid);
        CP_COMMIT();

        for (int i = tid; i < 1024; i += 256) {
            int r = i >> 3, j = i & 7;
            *(uint4*)&sQ[r*KST + j*8] = *(const uint4*)&qp[(size_t)r*DK_ + j*8];
        }
        __syncthreads();

        uint32_t qa[4][4];
        {
            uint32_t qaddr = smb + (uint32_t)(((warp*16 + (lane & 15))*KST + (lane >> 4)*8) * 2);
            #pragma unroll
            for (int ks = 0; ks < 4; ks++)
                LDSM_X4(qa[ks][0], qa[ks][1], qa[ks][2], qa[ks][3], qaddr + ks*32);
        }

        float oacc[32];
        #pragma unroll
        for (int i = 0; i < 32; i++) oacc[i] = 0.f;
        float l_lo = 0.f, l_hi = 0.f;
        int st = 0;

        for (int kb = kb0; kb < kend; kb += 64) {
            CP_WAIT(1);
            __syncthreads();

            {
                int stn = st + 2; if (stn >= 3) stn -= 3;
                if (kb + 128 < kend)
                    attn_prefetch(skb0 + stn*KVB, svb0 + stn*KVB, kp, vp, kb + 128, tid);
                CP_COMMIT();
            }

            const uint32_t kfbase = skb0 + st*KVB + kfo;
            const uint32_t vfbase = svb0 + st*KVB + vfo;

            float sacc[32];
            #pragma unroll
            for (int i = 0; i < 32; i++) sacc[i] = 0.f;
            #pragma unroll
            for (int ks = 0; ks < 4; ks++) {
                #pragma unroll
                for (int ntp = 0; ntp < 4; ntp++) {
                    uint32_t b0, b1, b2, b3;
                    LDSM_X4(b0, b1, b2, b3, kfbase + (uint32_t)((ntp*16*KST + ks*16) * 2));
                    MMA16816(sacc[(2*ntp)*4+0], sacc[(2*ntp)*4+1], sacc[(2*ntp)*4+2], sacc[(2*ntp)*4+3],
                             qa[ks][0], qa[ks][1], qa[ks][2], qa[ks][3], b0, b1);
                    MMA16816(sacc[(2*ntp+1)*4+0], sacc[(2*ntp+1)*4+1], sacc[(2*ntp+1)*4+2], sacc[(2*ntp+1)*4+3],
                             qa[ks][0], qa[ks][1], qa[ks][2], qa[ks][3], b2, b3);
                }
            }

            // ---- softmax (f16x2) interleaved with PV: pair jj feeds PV group kk=jj ----
            const bool partial = (kb < kstart) || (kb + 64 > kend);
            uint32_t ppack[16];
            float ls_lo = 0.f, ls_hi = 0.f;
            #pragma unroll
            for (int jj = 0; jj < 4; jj++) {
                #pragma unroll
                for (int q = 0; q < 2; q++) {
                    int j = 2*jj + q;
                    __half2 s_lo = __float22half2_rn(make_float2(sacc[4*j+0], sacc[4*j+1]));
                    __half2 s_hi = __float22half2_rn(make_float2(sacc[4*j+2], sacc[4*j+3]));
                    uint32_t plo = ex2_h2(*(uint32_t*)&s_lo);
                    uint32_t phi = ex2_h2(*(uint32_t*)&s_hi);
                    if (partial) {
                        int col = kb + j*8 + (lane & 3)*2;
                        uint32_t m = (((col >= kstart) & (col < kend)) ? 0x0000FFFFu : 0u)
                                   | (((col + 1 >= kstart) & (col + 1 < kend)) ? 0xFFFF0000u : 0u);
                        plo &= m; phi &= m;
                    }
                    ppack[2*j]   = plo;
                    ppack[2*j+1] = phi;
                    float2 f0 = __half22float2(*(__half2*)&plo);
                    float2 f1 = __half22float2(*(__half2*)&phi);
                    ls_lo += f0.x + f0.y;
                    ls_hi += f1.x + f1.y;
                }
                // PV for kk = jj (tensor work overlaps next pair's scalar softmax)
                #pragma unroll
                for (int dt = 0; dt < 4; dt++) {
                    uint32_t b0, b1, b2, b3;
                    LDSM_X4_T(b0, b1, b2, b3, vfbase + (uint32_t)((jj*16*KST + dt*16) * 2));
                    MMA16816(oacc[(2*dt)*4+0], oacc[(2*dt)*4+1], oacc[(2*dt)*4+2], oacc[(2*dt)*4+3],
                             ppack[4*jj+0], ppack[4*jj+1], ppack[4*jj+2], ppack[4*jj+3], b0, b1);
                    MMA16816(oacc[(2*dt+1)*4+0], oacc[(2*dt+1)*4+1], oacc[(2*dt+1)*4+2], oacc[(2*dt+1)*4+3],
                             ppack[4*jj+0], ppack[4*jj+1], ppack[4*jj+2], ppack[4*jj+3], b2, b3);
                }
            }
            ls_lo += __shfl_xor_sync(0xffffffffu, ls_lo, 1);
            ls_lo += __shfl_xor_sync(0xffffffffu, ls_lo, 2);
            ls_hi += __shfl_xor_sync(0xffffffffu, ls_hi, 1);
            ls_hi += __shfl_xor_sync(0xffffffffu, ls_hi, 2);
            l_lo += ls_lo;
            l_hi += ls_hi;

            st = (st + 1 == 3) ? 0 : st + 1;
        }

        const int r_lo = q0 + warp*16 + (lane >> 2);
        const int r_hi = r_lo + 8;
        const bool v_lo = (r_lo >= kstart) && (r_lo < kend);
        const bool v_hi = (r_hi >= kstart) && (r_hi < kend);
        const float inv_lo = v_lo ? 1.f / l_lo : 0.f;
        const float inv_hi = v_hi ? 1.f / l_hi : 0.f;
        __half* orow_lo = g_att + ((size_t)b*NN + r_lo)*DM_ + h*DK_;
        __half* orow_hi = g_att + ((size_t)b*NN + r_hi)*DM_ + h*DK_;
        #pragma unroll
        for (int j = 0; j < 8; j++) {
            int d = j*8 + (lane & 3)*2;
            float2 lo, hi;
            if (v_lo) { lo.x = oacc[4*j+0]*inv_lo; lo.y = oacc[4*j+1]*inv_lo; }
            else      { lo.x = vmS[d]; lo.y = vmS[d+1]; }
            if (v_hi) { hi.x = oacc[4*j+2]*inv_hi; hi.y = oacc[4*j+3]*inv_hi; }
            else      { hi.x = vmS[d]; hi.y = vmS[d+1]; }
            __half2 lo2 = __float22half2_rn(lo);
            __half2 hi2 = __float22half2_rn(hi);
            *(uint32_t*)&orow_lo[d] = *(uint32_t*)&lo2;
            *(uint32_t*)&orow_hi[d] = *(uint32_t*)&hi2;
        }
    }
}

// ---------------- output GEMM, fp16 HMMA, full cp.async, 3-stage B ----------------
__global__ void __launch_bounds__(128) out_hmma_kernel(const float* __restrict__ bo,
                                                       float* __restrict__ out)
{
    extern __shared__ __align__(16) unsigned char dynsm[];
    const uint32_t sab = smem_u32(dynsm);
    const uint32_t sbb = sab + 4*GTB;

    const int tid = threadIdx.x, lane = tid & 31, warp = tid >> 5;
    const int m0 = blockIdx.y * 64;
    const int h  = blockIdx.x;
    const __half* wt = g_wt + (size_t)3 * (DM_*DIN_) + (size_t)(h*64)*DIN_;

    {
        const __half* ap = g_att + (size_t)m0*DM_;
        #pragma unroll
        for (int u = 0; u < 16; u++) {
            int i = tid + u*128;
            int r = i >> 5, j8 = i & 31;
            int t = j8 >> 3, jj = j8 & 7;
            CP_ASYNC16(sab + (uint32_t)(t*GTB) + (uint32_t)((r*GST + jj*8)*2),
                       ap + (size_t)r*DM_ + j8*8);
        }
        CP_COMMIT();
    }
    gemm_prefetch_b(sbb, wt, tid);
    CP_COMMIT();
    gemm_prefetch_b(sbb + GTB, wt + 64, tid);
    CP_COMMIT();

    const uint32_t afo = (uint32_t)(((warp*16 + (lane & 15))*GST + (lane >> 4)*8) * 2);
    const uint32_t bfo = (uint32_t)(((((lane & 7) + ((lane >> 4) << 3))*GST) + ((lane >> 3) & 1)*8) * 2);

    float acc[32];
    #pragma unroll
    for (int i = 0; i < 32; i++) acc[i] = 0.f;

    for (int t = 0; t < 4; t++) {
        CP_WAIT(1);
        __syncthreads();
        {
            int tn = t + 2;
            if (tn < 4)
                gemm_prefetch_b(sbb + (uint32_t)((tn % 3)*GTB), wt + tn*64, tid);
            CP_COMMIT();
        }

        uint32_t af[4][4];
        const uint32_t afb = sab + (uint32_t)(t*GTB) + afo;
        #pragma unroll
        for (int ks = 0; ks < 4; ks++)
            LDSM_X4(af[ks][0], af[ks][1], af[ks][2], af[ks][3], afb + ks*32);

        const uint32_t bfb = sbb + (uint32_t)((t % 3)*GTB) + bfo;
        #pragma unroll
        for (int ks = 0; ks < 4; ks++) {
            #pragma unroll
            for (int ntp = 0; ntp < 4; ntp++) {
                uint32_t b0, b1, b2, b3;
                LDSM_X4(b0, b1, b2, b3, bfb + (uint32_t)((ntp*16*GST + ks*16) * 2));
                MMA16816(acc[(2*ntp)*4+0], acc[(2*ntp)*4+1], acc[(2*ntp)*4+2], acc[(2*ntp)*4+3],
                         af[ks][0], af[ks][1], af[ks][2], af[ks][3], b0, b1);
                MMA16816(acc[(2*ntp+1)*4+0], acc[(2*ntp+1)*4+1], acc[(2*ntp+1)*4+2], acc[(2*ntp+1)*4+3],
                         af[ks][0], af[ks][1], af[ks][2], af[ks][3], b2, b3);
            }
        }
    }

    const int r_lo = m0 + warp*16 + (lane >> 2);
    const int r_hi = r_lo + 8;
    #pragma unroll
    for (int j = 0; j < 8; j++) {
        int d = j*8 + (lane & 3)*2;
        float2 bv2 = *(const float2*)&bo[h*64 + d];
        float2 lo = make_float2(acc[4*j+0] + bv2.x, acc[4*j+1] + bv2.y);
        float2 hi = make_float2(acc[4*j+2] + bv2.x, acc[4*j+3] + bv2.y);
        *(float2*)&out[(size_t)r_lo*DM_ + h*64 + d] = lo;
        *(float2*)&out[(size_t)r_hi*DM_ + h*64 + d] = hi;
    }
}

// ---------------- launch ----------------
extern "C" void kernel_launch(void* const* d_in, const int* in_sizes, int n_in,
                              void* d_out, int out_size) {
    const float* x    = (const float*)d_in[0];
    const int*   mask = (const int*)  d_in[1];
    const float* Wq = (const float*)d_in[2]; const float* bq = (const float*)d_in[3];
    const float* Wk = (const float*)d_in[4]; const float* bk = (const float*)d_in[5];
    const float* Wv = (const float*)d_in[6]; const float* bv = (const float*)d_in[7];
    const float* Wo = (const float*)d_in[8]; const float* bo = (const float*)d_in[9];
    float* out = (float*)d_out;

    const int gemm_smem = 4*9216 + 3*9216;            // 64512
    const int attn_smem = 128*KST*2 + 6*64*KST*2;     // 73728
    cudaFuncSetAttribute(qkv_hmma_kernel, cudaFuncAttributeMaxDynamicSharedMemorySize, gemm_smem);
    cudaFuncSetAttribute(out_hmma_kernel, cudaFuncAttributeMaxDynamicSharedMemorySize, gemm_smem);
    cudaFuncSetAttribute(attn_mma_kernel, cudaFuncAttributeMaxDynamicSharedMemorySize, attn_smem);

    prep_kernel<<<dim3(32, 8, 6), dim3(32, 8)>>>(Wq, Wk, Wv, Wo, mask, x);
    qkv_hmma_kernel<<<dim3(DM_/64, ROWS/64), 128, gemm_smem>>>(bq, bk, bv);
    vmean_part_kernel<<<dim3(33, 8), 256>>>();
    attn_mma_kernel<<<PERSIST, 256, attn_smem>>>();
    out_hmma_kernel<<<dim3(DM_/64, ROWS/64), 128, gemm_smem>>>(bo, out);
}

// round 15
// speedup vs baseline: 1.3050x; 1.3050x over previous
#include <cuda_runtime.h>
#include <cuda_fp16.h>
#include <cstdint>

#define BB   8
#define NN   2048
#define DIN_ 256
#define DM_  256
#define NH_  4
#define DK_  64
#define ROWS (BB*NN)
#define NTILES 512
#define PERSIST 296

// ---------------- scratch (no allocations allowed) ----------------
__device__ __half g_qb[BB*NH_*NN*DK_];   // pre-scaled by scale*log2(e)
__device__ __half g_kb[BB*NH_*NN*DK_];
__device__ __half g_vb[BB*NH_*NN*DK_];
__device__ __half g_xb[ROWS*DIN_];       // x in fp16
__device__ __half g_wt[4*DM_*DIN_];      // W^T [z][n][k], fp16 (q,k,v,o)
__device__ __half g_att[ROWS*DM_];       // fp16 [b*n][h*64+d]
__device__ float g_vpart[BB*NH_*8*DK_];
__device__ int   g_start[BB];
__device__ int   g_end[BB];              // exclusive bound = last-true index
__device__ int   g_work;                 // persistent-CTA work counter
__device__ short g_order[NTILES];        // LPT tile order

#define SCL2E 0.18033688f   /* 0.125 * log2(e) */

// ---------------- small asm helpers ----------------
__device__ __forceinline__ uint32_t smem_u32(const void* p) {
    uint32_t a;
    asm("{ .reg .u64 t; cvta.to.shared.u64 t, %1; cvt.u32.u64 %0, t; }" : "=r"(a) : "l"(p));
    return a;
}
__device__ __forceinline__ uint32_t ex2_h2(uint32_t s) {
    uint32_t y; asm("ex2.approx.f16x2 %0, %1;" : "=r"(y) : "r"(s)); return y;
}
#define LDSM_X4(r0,r1,r2,r3,addr) \
    asm volatile("ldmatrix.sync.aligned.m8n8.x4.shared.b16 {%0,%1,%2,%3}, [%4];" \
        : "=r"(r0), "=r"(r1), "=r"(r2), "=r"(r3) : "r"(addr))
#define LDSM_X4_T(r0,r1,r2,r3,addr) \
    asm volatile("ldmatrix.sync.aligned.m8n8.x4.trans.shared.b16 {%0,%1,%2,%3}, [%4];" \
        : "=r"(r0), "=r"(r1), "=r"(r2), "=r"(r3) : "r"(addr))
#define MMA16816(c0,c1,c2,c3,a0,a1,a2,a3,b0,b1) \
    asm volatile("mma.sync.aligned.m16n8k16.row.col.f32.f16.f16.f32 " \
        "{%0,%1,%2,%3}, {%4,%5,%6,%7}, {%8,%9}, {%0,%1,%2,%3};" \
        : "+f"(c0), "+f"(c1), "+f"(c2), "+f"(c3) \
        : "r"(a0), "r"(a1), "r"(a2), "r"(a3), "r"(b0), "r"(b1))
#define CP_ASYNC16(smem, gptr) \
    asm volatile("cp.async.cg.shared.global [%0], [%1], 16;" :: "r"(smem), "l"(gptr))
#define CP_COMMIT() asm volatile("cp.async.commit_group;" ::: "memory")
#define CP_WAIT(n)  asm volatile("cp.async.wait_group %0;" :: "n"(n) : "memory")

// ---------------- prep: W^T cvt (z<4) + mask scan (z==4) + x cvt (z==5) ----------------
__global__ void prep_kernel(const float* __restrict__ Wq, const float* __restrict__ Wk,
                            const float* __restrict__ Wv, const float* __restrict__ Wo,
                            const int* __restrict__ mask, const float* __restrict__ x) {
    const int z = blockIdx.z;
    const int tid = threadIdx.y * 32 + threadIdx.x;
    if (z == 5) {            // x fp32 -> fp16
        int bid = blockIdx.y * 32 + blockIdx.x;
        const float4* xs = (const float4*)x;
        uint2* xd = (uint2*)g_xb;
        #pragma unroll
        for (int u = 0; u < 16; u++) {
            int idx = bid*4096 + u*256 + tid;
            float4 a = xs[idx];
            __half2 h0 = __float22half2_rn(make_float2(a.x, a.y));
            __half2 h1 = __float22half2_rn(make_float2(a.z, a.w));
            xd[idx] = make_uint2(*(uint32_t*)&h0, *(uint32_t*)&h1);
        }
        return;
    }
    if (z == 4) {            // mask scan (+ work-counter reset)
        if (blockIdx.y != 0 || blockIdx.x >= BB) return;
        int b = blockIdx.x;
        if (b == 0 && tid == 0) g_work = 0;
        __shared__ int smin, smax;
        if (tid == 0) { smin = NN; smax = -1; }
        __syncthreads();
        int lmin = NN, lmax = -1;
        for (int i = tid; i < NN; i += 256) {
            if (mask[b*NN + i]) { lmin = min(lmin, i); lmax = max(lmax, i); }
        }
        atomicMin(&smin, lmin);
        atomicMax(&smax, lmax);
        __syncthreads();
        if (tid == 0) { g_start[b] = smin; g_end[b] = smax; }
        return;
    }
    if (blockIdx.x >= 8) return;
    __shared__ float t[32][33];
    const float* W = z == 0 ? Wq : z == 1 ? Wk : z == 2 ? Wv : Wo;
    __half* wt = g_wt + (size_t)z * (DM_*DIN_);
    int n0 = blockIdx.x * 32, k0 = blockIdx.y * 32;
    for (int i = threadIdx.y; i < 32; i += 8)
        t[i][threadIdx.x] = W[(size_t)(k0 + i)*DM_ + n0 + threadIdx.x];
    __syncthreads();
    for (int i = threadIdx.y; i < 32; i += 8)
        wt[(size_t)(n0 + i)*DIN_ + k0 + threadIdx.x] = __float2half_rn(t[threadIdx.x][i]);
}

// ---------------- fused QKV GEMM, fp16 HMMA, full cp.async, 3-stage B ----------------
#define GST 72
#define GTB ((uint32_t)(64*GST*2))

__device__ __forceinline__ void gemm_prefetch_b(uint32_t dstb, const __half* wp, int tid) {
    #pragma unroll
    for (int u = 0; u < 4; u++) {
        int i = tid + u*128;
        int r = i >> 3, j = i & 7;
        CP_ASYNC16(dstb + (uint32_t)((r*GST + j*8)*2), wp + (size_t)r*DIN_ + j*8);
    }
}

__global__ void __launch_bounds__(128) qkv_hmma_kernel(const float* __restrict__ bq,
                                                       const float* __restrict__ bk,
                                                       const float* __restrict__ bv)
{
    extern __shared__ __align__(16) unsigned char dynsm[];
    const uint32_t sab = smem_u32(dynsm);
    const uint32_t sbb = sab + 4*GTB;

    const int tid = threadIdx.x, lane = tid & 31, warp = tid >> 5;
    const int m0 = blockIdx.y * 64;
    const int h  = blockIdx.x;

    {
        const __half* xp = g_xb + (size_t)m0*DIN_;
        #pragma unroll
        for (int u = 0; u < 16; u++) {
            int i = tid + u*128;
            int r = i >> 5, j8 = i & 31;
            int t = j8 >> 3, jj = j8 & 7;
            CP_ASYNC16(sab + (uint32_t)(t*GTB) + (uint32_t)((r*GST + jj*8)*2),
                       xp + (size_t)r*DIN_ + j8*8);
        }
        CP_COMMIT();
    }
    gemm_prefetch_b(sbb, g_wt + (size_t)(h*64)*DIN_, tid);
    CP_COMMIT();
    gemm_prefetch_b(sbb + GTB, g_wt + (size_t)(h*64)*DIN_ + 64, tid);
    CP_COMMIT();

    const uint32_t afo = (uint32_t)(((warp*16 + (lane & 15))*GST + (lane >> 4)*8) * 2);
    const uint32_t bfo = (uint32_t)(((((lane & 7) + ((lane >> 4) << 3))*GST) + ((lane >> 3) & 1)*8) * 2);

    float acc[32];
    #pragma unroll
    for (int i = 0; i < 32; i++) acc[i] = 0.f;

    for (int t = 0; t < 12; t++) {
        const int z = t >> 2, k0 = t & 3;
        CP_WAIT(1);
        __syncthreads();
        {
            int tn = t + 2;
            if (tn < 12) {
                int zn = tn >> 2, kn = tn & 3;
                int stn = tn % 3;
                gemm_prefetch_b(sbb + (uint32_t)(stn*GTB),
                                g_wt + (size_t)zn*(DM_*DIN_) + (size_t)(h*64)*DIN_ + kn*64, tid);
            }
            CP_COMMIT();
        }

        uint32_t af[4][4];
        const uint32_t afb = sab + (uint32_t)(k0*GTB) + afo;
        #pragma unroll
        for (int ks = 0; ks < 4; ks++)
            LDSM_X4(af[ks][0], af[ks][1], af[ks][2], af[ks][3], afb + ks*32);

        const uint32_t bfb = sbb + (uint32_t)((t % 3)*GTB) + bfo;
        #pragma unroll
        for (int ks = 0; ks < 4; ks++) {
            #pragma unroll
            for (int ntp = 0; ntp < 4; ntp++) {
                uint32_t b0, b1, b2, b3;
                LDSM_X4(b0, b1, b2, b3, bfb + (uint32_t)((ntp*16*GST + ks*16) * 2));
                MMA16816(acc[(2*ntp)*4+0], acc[(2*ntp)*4+1], acc[(2*ntp)*4+2], acc[(2*ntp)*4+3],
                         af[ks][0], af[ks][1], af[ks][2], af[ks][3], b0, b1);
                MMA16816(acc[(2*ntp+1)*4+0], acc[(2*ntp+1)*4+1], acc[(2*ntp+1)*4+2], acc[(2*ntp+1)*4+3],
                         af[ks][0], af[ks][1], af[ks][2], af[ks][3], b2, b3);
            }
        }

        if (k0 == 3) {
            const float* bias = z == 0 ? bq : z == 1 ? bk : bv;
            __half* dst = z == 0 ? g_qb : z == 1 ? g_kb : g_vb;
            const float os = z == 0 ? SCL2E : 1.f;
            const int r_lo = m0 + warp*16 + (lane >> 2);
            const int r_hi = r_lo + 8;
            const int b_lo = r_lo >> 11, n_lo = r_lo & (NN - 1);
            const int b_hi = r_hi >> 11, n_hi = r_hi & (NN - 1);
            __half* p_lo = dst + ((((size_t)b_lo*NH_ + h)*NN) + n_lo)*DK_;
            __half* p_hi = dst + ((((size_t)b_hi*NH_ + h)*NN) + n_hi)*DK_;
            #pragma unroll
            for (int j = 0; j < 8; j++) {
                int d = j*8 + (lane & 3)*2;
                float2 bv2 = *(const float2*)&bias[h*64 + d];
                __half2 lo = __float22half2_rn(make_float2((acc[4*j+0] + bv2.x)*os,
                                                           (acc[4*j+1] + bv2.y)*os));
                __half2 hi = __float22half2_rn(make_float2((acc[4*j+2] + bv2.x)*os,
                                                           (acc[4*j+3] + bv2.y)*os));
                *(uint32_t*)&p_lo[d] = *(uint32_t*)&lo;
                *(uint32_t*)&p_hi[d] = *(uint32_t*)&hi;
            }
            #pragma unroll
            for (int i = 0; i < 32; i++) acc[i] = 0.f;
        }
    }
}

// ---------------- vmean partials + tile-order sorter ----------------
__global__ void vmean_part_kernel() {      // grid (33, 8), block 256
    if (blockIdx.x == 32) {                // LPT sorter (one thread)
        if (blockIdx.y == 0 && threadIdx.x == 0) {
            int lens[BB], ord[BB];
            for (int b = 0; b < BB; b++) {
                lens[b] = g_end[b] - (g_start[b] & ~63);
                ord[b] = b;
            }
            for (int i = 0; i < BB; i++)
                for (int j = i + 1; j < BB; j++)
                    if (lens[ord[j]] > lens[ord[i]]) { int t = ord[i]; ord[i] = ord[j]; ord[j] = t; }
            int p = 0;
            for (int r = 0; r < BB; r++)
                for (int h = 0; h < NH_; h++)
                    for (int qt = 0; qt < 16; qt++)
                        g_order[p++] = (short)((((ord[r]*NH_ + h) << 4)) | qt);
        }
        return;
    }
    __shared__ float2 red[256];
    int bh = blockIdx.x, seg = blockIdx.y;
    int p = threadIdx.x & 31, grp = threadIdx.x >> 5;
    const __half* vptr = g_vb + ((size_t)bh*NN + seg*256 + grp*32)*DK_;
    float2 s = make_float2(0.f, 0.f);
    #pragma unroll 8
    for (int r = 0; r < 32; r++) {
        __half2 v = *(const __half2*)&vptr[(size_t)r*DK_ + p*2];
        float2 f = __half22float2(v);
        s.x += f.x; s.y += f.y;
    }
    red[threadIdx.x] = s;
    __syncthreads();
    if (grp == 0) {
        float2 acc = red[p];
        #pragma unroll
        for (int g = 1; g < 8; g++) {
            float2 r2 = red[p + 32*g];
            acc.x += r2.x; acc.y += r2.y;
        }
        *(float2*)&g_vpart[((size_t)bh*8 + seg)*DK_ + p*2] = acc;
    }
}

// ---------------- HMMA fp16 flash attention: persistent CTAs, LPT, f16x2 softmax ----------------
#define KST 72
#define QB  ((uint32_t)(128*KST*2))
#define KVB ((uint32_t)(64*KST*2))

__device__ __forceinline__ void attn_prefetch(uint32_t skb, uint32_t svb,
                                              const __half* kp, const __half* vp,
                                              int kb, int tid) {
    #pragma unroll
    for (int u = 0; u < 2; u++) {
        int i = tid + u*256;
        int r = i >> 3, j = i & 7;
        int gr = kb + r; if (gr > NN - 1) gr = NN - 1;
        uint32_t so = (uint32_t)((r*KST + j*8) * 2);
        CP_ASYNC16(skb + so, kp + (size_t)gr*DK_ + j*8);
        CP_ASYNC16(svb + so, vp + (size_t)gr*DK_ + j*8);
    }
}

__global__ void __launch_bounds__(256) attn_mma_kernel() {
    extern __shared__ __align__(16) unsigned char dynsm[];
    __shared__ float vmS[64];
    __shared__ int sIdx;
    __half* sQ = (__half*)dynsm;
    const uint32_t smb = smem_u32(dynsm);
    const uint32_t skb0 = smb + QB;
    const uint32_t svb0 = smb + QB + 3*KVB;

    const int tid = threadIdx.x, lane = tid & 31, warp = tid >> 5;
    const uint32_t kfo = (uint32_t)(((((lane & 7) + ((lane >> 4) << 3))*KST) + ((lane >> 3) & 1)*8) * 2);
    const uint32_t vfo = (uint32_t)(((((lane & 7) + (((lane >> 3) & 1) << 3))*KST) + (lane >> 4)*8) * 2);

    for (;;) {
        if (tid == 0) sIdx = atomicAdd(&g_work, 1);
        __syncthreads();               // broadcast idx; fences smem reuse from prev tile
        const int idx = sIdx;
        if (idx >= NTILES) break;
        const int tile = g_order[idx];
        const int qt = tile & 15, bh = tile >> 4;
        const int b = bh >> 2, h = bh & 3;
        const int q0 = qt * 128;
        const int kstart = g_start[b], kend = g_end[b];
        __half* outbase = g_att + ((size_t)b*NN + q0)*DM_ + h*DK_;

        if (tid < 64) {
            float s = 0.f;
            #pragma unroll
            for (int seg = 0; seg < 8; seg++)
                s += g_vpart[((size_t)bh*8 + seg)*DK_ + tid];
            vmS[tid] = s * (1.f/NN);
        }
        __syncthreads();

        const bool any = (q0 < kend) && (q0 + 127 >= kstart);
        if (!any) {
            int r = tid >> 1, c0 = (tid & 1) * 32;
            #pragma unroll
            for (int j = 0; j < 8; j++) {
                __half2 a = __float22half2_rn(make_float2(vmS[c0+j*4],   vmS[c0+j*4+1]));
                __half2 c = __float22half2_rn(make_float2(vmS[c0+j*4+2], vmS[c0+j*4+3]));
                *(uint2*)&outbase[(size_t)r*DM_ + c0 + j*4] =
                    make_uint2(*(uint32_t*)&a, *(uint32_t*)&c);
            }
            continue;
        }

        const __half* qp = g_qb + ((size_t)bh*NN + q0)*DK_;
        const __half* kp = g_kb + (size_t)bh*NN*DK_;
        const __half* vp = g_vb + (size_t)bh*NN*DK_;
        const int kb0 = kstart & ~63;

        attn_prefetch(skb0, svb0, kp, vp, kb0, tid);
        CP_COMMIT();
        if (kb0 + 64 < kend)
            attn_prefetch(skb0 + KVB, svb0 + KVB, kp, vp, kb0 + 64, tid);
        CP_COMMIT();

        for (int i = tid; i < 1024; i += 256) {
            int r = i >> 3, j = i & 7;
            *(uint4*)&sQ[r*KST + j*8] = *(const uint4*)&qp[(size_t)r*DK_ + j*8];
        }
        __syncthreads();

        uint32_t qa[4][4];
        {
            uint32_t qaddr = smb + (uint32_t)(((warp*16 + (lane & 15))*KST + (lane >> 4)*8) * 2);
            #pragma unroll
            for (int ks = 0; ks < 4; ks++)
                LDSM_X4(qa[ks][0], qa[ks][1], qa[ks][2], qa[ks][3], qaddr + ks*32);
        }

        float oacc[32];
        #pragma unroll
        for (int i = 0; i < 32; i++) oacc[i] = 0.f;
        float l_lo = 0.f, l_hi = 0.f;
        int st = 0;

        for (int kb = kb0; kb < kend; kb += 64) {
            CP_WAIT(1);
            __syncthreads();

            {
                int stn = st + 2; if (stn >= 3) stn -= 3;
                if (kb + 128 < kend)
                    attn_prefetch(skb0 + stn*KVB, svb0 + stn*KVB, kp, vp, kb + 128, tid);
                CP_COMMIT();
            }

            const uint32_t kfbase = skb0 + st*KVB + kfo;
            const uint32_t vfbase = svb0 + st*KVB + vfo;

            float sacc[32];
            #pragma unroll
            for (int i = 0; i < 32; i++) sacc[i] = 0.f;
            #pragma unroll
            for (int ks = 0; ks < 4; ks++) {
                #pragma unroll
                for (int ntp = 0; ntp < 4; ntp++) {
                    uint32_t b0, b1, b2, b3;
                    LDSM_X4(b0, b1, b2, b3, kfbase + (uint32_t)((ntp*16*KST + ks*16) * 2));
                    MMA16816(sacc[(2*ntp)*4+0], sacc[(2*ntp)*4+1], sacc[(2*ntp)*4+2], sacc[(2*ntp)*4+3],
                             qa[ks][0], qa[ks][1], qa[ks][2], qa[ks][3], b0, b1);
                    MMA16816(sacc[(2*ntp+1)*4+0], sacc[(2*ntp+1)*4+1], sacc[(2*ntp+1)*4+2], sacc[(2*ntp+1)*4+3],
                             qa[ks][0], qa[ks][1], qa[ks][2], qa[ks][3], b2, b3);
                }
            }

            // ---- softmax via ex2.approx.f16x2 (packed, half the MUFU ops) ----
            const bool partial = (kb < kstart) || (kb + 64 > kend);
            uint32_t ppack[16];
            float ls_lo = 0.f, ls_hi = 0.f;
            #pragma unroll
            for (int j = 0; j < 8; j++) {
                __half2 s_lo = __float22half2_rn(make_float2(sacc[4*j+0], sacc[4*j+1]));
                __half2 s_hi = __float22half2_rn(make_float2(sacc[4*j+2], sacc[4*j+3]));
                uint32_t plo = ex2_h2(*(uint32_t*)&s_lo);
                uint32_t phi = ex2_h2(*(uint32_t*)&s_hi);
                if (partial) {
                    int col = kb + j*8 + (lane & 3)*2;
                    uint32_t m = (((col >= kstart) & (col < kend)) ? 0x0000FFFFu : 0u)
                               | (((col + 1 >= kstart) & (col + 1 < kend)) ? 0xFFFF0000u : 0u);
                    plo &= m; phi &= m;
                }
                ppack[2*j]   = plo;
                ppack[2*j+1] = phi;
                float2 f0 = __half22float2(*(__half2*)&plo);
                float2 f1 = __half22float2(*(__half2*)&phi);
                ls_lo += f0.x + f0.y;
                ls_hi += f1.x + f1.y;
            }
            ls_lo += __shfl_xor_sync(0xffffffffu, ls_lo, 1);
            ls_lo += __shfl_xor_sync(0xffffffffu, ls_lo, 2);
            ls_hi += __shfl_xor_sync(0xffffffffu, ls_hi, 1);
            ls_hi += __shfl_xor_sync(0xffffffffu, ls_hi, 2);
            l_lo += ls_lo;
            l_hi += ls_hi;

            #pragma unroll
            for (int kk = 0; kk < 4; kk++) {
                #pragma unroll
                for (int dt = 0; dt < 4; dt++) {
                    uint32_t b0, b1, b2, b3;
                    LDSM_X4_T(b0, b1, b2, b3, vfbase + (uint32_t)((kk*16*KST + dt*16) * 2));
                    MMA16816(oacc[(2*dt)*4+0], oacc[(2*dt)*4+1], oacc[(2*dt)*4+2], oacc[(2*dt)*4+3],
                             ppack[4*kk+0], ppack[4*kk+1], ppack[4*kk+2], ppack[4*kk+3], b0, b1);
                    MMA16816(oacc[(2*dt+1)*4+0], oacc[(2*dt+1)*4+1], oacc[(2*dt+1)*4+2], oacc[(2*dt+1)*4+3],
                             ppack[4*kk+0], ppack[4*kk+1], ppack[4*kk+2], ppack[4*kk+3], b2, b3);
                }
            }
            st = (st + 1 == 3) ? 0 : st + 1;
        }

        const int r_lo = q0 + warp*16 + (lane >> 2);
        const int r_hi = r_lo + 8;
        const bool v_lo = (r_lo >= kstart) && (r_lo < kend);
        const bool v_hi = (r_hi >= kstart) && (r_hi < kend);
        const float inv_lo = v_lo ? 1.f / l_lo : 0.f;
        const float inv_hi = v_hi ? 1.f / l_hi : 0.f;
        __half* orow_lo = g_att + ((size_t)b*NN + r_lo)*DM_ + h*DK_;
        __half* orow_hi = g_att + ((size_t)b*NN + r_hi)*DM_ + h*DK_;
        #pragma unroll
        for (int j = 0; j < 8; j++) {
            int d = j*8 + (lane & 3)*2;
            float2 lo, hi;
            if (v_lo) { lo.x = oacc[4*j+0]*inv_lo; lo.y = oacc[4*j+1]*inv_lo; }
            else      { lo.x = vmS[d]; lo.y = vmS[d+1]; }
            if (v_hi) { hi.x = oacc[4*j+2]*inv_hi; hi.y = oacc[4*j+3]*inv_hi; }
            else      { hi.x = vmS[d]; hi.y = vmS[d+1]; }
            __half2 lo2 = __float22half2_rn(lo);
            __half2 hi2 = __float22half2_rn(hi);
            *(uint32_t*)&orow_lo[d] = *(uint32_t*)&lo2;
            *(uint32_t*)&orow_hi[d] = *(uint32_t*)&hi2;
        }
    }
}

// ---------------- output GEMM, fp16 HMMA, full cp.async, 3-stage B ----------------
__global__ void __launch_bounds__(128) out_hmma_kernel(const float* __restrict__ bo,
                                                       float* __restrict__ out)
{
    extern __shared__ __align__(16) unsigned char dynsm[];
    const uint32_t sab = smem_u32(dynsm);
    const uint32_t sbb = sab + 4*GTB;

    const int tid = threadIdx.x, lane = tid & 31, warp = tid >> 5;
    const int m0 = blockIdx.y * 64;
    const int h  = blockIdx.x;
    const __half* wt = g_wt + (size_t)3 * (DM_*DIN_) + (size_t)(h*64)*DIN_;

    {
        const __half* ap = g_att + (size_t)m0*DM_;
        #pragma unroll
        for (int u = 0; u < 16; u++) {
            int i = tid + u*128;
            int r = i >> 5, j8 = i & 31;
            int t = j8 >> 3, jj = j8 & 7;
            CP_ASYNC16(sab + (uint32_t)(t*GTB) + (uint32_t)((r*GST + jj*8)*2),
                       ap + (size_t)r*DM_ + j8*8);
        }
        CP_COMMIT();
    }
    gemm_prefetch_b(sbb, wt, tid);
    CP_COMMIT();
    gemm_prefetch_b(sbb + GTB, wt + 64, tid);
    CP_COMMIT();

    const uint32_t afo = (uint32_t)(((warp*16 + (lane & 15))*GST + (lane >> 4)*8) * 2);
    const uint32_t bfo = (uint32_t)(((((lane & 7) + ((lane >> 4) << 3))*GST) + ((lane >> 3) & 1)*8) * 2);

    float acc[32];
    #pragma unroll
    for (int i = 0; i < 32; i++) acc[i] = 0.f;

    for (int t = 0; t < 4; t++) {
        CP_WAIT(1);
        __syncthreads();
        {
            int tn = t + 2;
            if (tn < 4)
                gemm_prefetch_b(sbb + (uint32_t)((tn % 3)*GTB), wt + tn*64, tid);
            CP_COMMIT();
        }

        uint32_t af[4][4];
        const uint32_t afb = sab + (uint32_t)(t*GTB) + afo;
        #pragma unroll
        for (int ks = 0; ks < 4; ks++)
            LDSM_X4(af[ks][0], af[ks][1], af[ks][2], af[ks][3], afb + ks*32);

        const uint32_t bfb = sbb + (uint32_t)((t % 3)*GTB) + bfo;
        #pragma unroll
        for (int ks = 0; ks < 4; ks++) {
            #pragma unroll
            for (int ntp = 0; ntp < 4; ntp++) {
                uint32_t b0, b1, b2, b3;
                LDSM_X4(b0, b1, b2, b3, bfb + (uint32_t)((ntp*16*GST + ks*16) * 2));
                MMA16816(acc[(2*ntp)*4+0], acc[(2*ntp)*4+1], acc[(2*ntp)*4+2], acc[(2*ntp)*4+3],
                         af[ks][0], af[ks][1], af[ks][2], af[ks][3], b0, b1);
                MMA16816(acc[(2*ntp+1)*4+0], acc[(2*ntp+1)*4+1], acc[(2*ntp+1)*4+2], acc[(2*ntp+1)*4+3],
                         af[ks][0], af[ks][1], af[ks][2], af[ks][3], b2, b3);
            }
        }
    }

    const int r_lo = m0 + warp*16 + (lane >> 2);
    const int r_hi = r_lo + 8;
    #pragma unroll
    for (int j = 0; j < 8; j++) {
        int d = j*8 + (lane & 3)*2;
        float2 bv2 = *(const float2*)&bo[h*64 + d];
        float2 lo = make_float2(acc[4*j+0] + bv2.x, acc[4*j+1] + bv2.y);
        float2 hi = make_float2(acc[4*j+2] + bv2.x, acc[4*j+3] + bv2.y);
        *(float2*)&out[(size_t)r_lo*DM_ + h*64 + d] = lo;
        *(float2*)&out[(size_t)r_hi*DM_ + h*64 + d] = hi;
    }
}

// ---------------- launch ----------------
extern "C" void kernel_launch(void* const* d_in, const int* in_sizes, int n_in,
                              void* d_out, int out_size) {
    const float* x    = (const float*)d_in[0];
    const int*   mask = (const int*)  d_in[1];
    const float* Wq = (const float*)d_in[2]; const float* bq = (const float*)d_in[3];
    const float* Wk = (const float*)d_in[4]; const float* bk = (const float*)d_in[5];
    const float* Wv = (const float*)d_in[6]; const float* bv = (const float*)d_in[7];
    const float* Wo = (const float*)d_in[8]; const float* bo = (const float*)d_in[9];
    float* out = (float*)d_out;

    const int gemm_smem = 4*9216 + 3*9216;            // 64512
    const int attn_smem = 128*KST*2 + 6*64*KST*2;     // 73728
    cudaFuncSetAttribute(qkv_hmma_kernel, cudaFuncAttributeMaxDynamicSharedMemorySize, gemm_smem);
    cudaFuncSetAttribute(out_hmma_kernel, cudaFuncAttributeMaxDynamicSharedMemorySize, gemm_smem);
    cudaFuncSetAttribute(attn_mma_kernel, cudaFuncAttributeMaxDynamicSharedMemorySize, attn_smem);

    prep_kernel<<<dim3(32, 8, 6), dim3(32, 8)>>>(Wq, Wk, Wv, Wo, mask, x);
    qkv_hmma_kernel<<<dim3(DM_/64, ROWS/64), 128, gemm_smem>>>(bq, bk, bv);
    vmean_part_kernel<<<dim3(33, 8), 256>>>();
    attn_mma_kernel<<<PERSIST, 256, attn_smem>>>();
    out_hmma_kernel<<<dim3(DM_/64, ROWS/64), 128, gemm_smem>>>(bo, out);
}

// round 16
// speedup vs baseline: 1.3282x; 1.0177x over previous
#include <cuda_runtime.h>
#include <cuda_fp16.h>
#include <cstdint>

#define BB   8
#define NN   2048
#define DIN_ 256
#define DM_  256
#define NH_  4
#define DK_  64
#define ROWS (BB*NN)
#define NTILES 512
#define PERSIST 296

// ---------------- scratch (no allocations allowed) ----------------
__device__ __half g_qb[BB*NH_*NN*DK_];   // pre-scaled by scale*log2(e)
__device__ __half g_kb[BB*NH_*NN*DK_];
__device__ __half g_vb[BB*NH_*NN*DK_];
__device__ __half g_xb[ROWS*DIN_];       // x in fp16
__device__ __half g_wt[4*DM_*DIN_];      // W^T [z][n][k], fp16 (q,k,v,o)
__device__ __half g_att[ROWS*DM_];       // fp16 [b*n][h*64+d]
__device__ float g_vpart[BB*NH_*32*DK_]; // per-qkv-CTA V column partials
__device__ int   g_start[BB];
__device__ int   g_end[BB];              // exclusive bound = last-true index
__device__ int   g_work;                 // persistent-CTA work counter
__device__ short g_order[NTILES];        // LPT tile order

#define SCL2E 0.18033688f   /* 0.125 * log2(e) */

// ---------------- small asm helpers ----------------
__device__ __forceinline__ uint32_t smem_u32(const void* p) {
    uint32_t a;
    asm("{ .reg .u64 t; cvta.to.shared.u64 t, %1; cvt.u32.u64 %0, t; }" : "=r"(a) : "l"(p));
    return a;
}
__device__ __forceinline__ uint32_t ex2_h2(uint32_t s) {
    uint32_t y; asm("ex2.approx.f16x2 %0, %1;" : "=r"(y) : "r"(s)); return y;
}
#define LDSM_X4(r0,r1,r2,r3,addr) \
    asm volatile("ldmatrix.sync.aligned.m8n8.x4.shared.b16 {%0,%1,%2,%3}, [%4];" \
        : "=r"(r0), "=r"(r1), "=r"(r2), "=r"(r3) : "r"(addr))
#define LDSM_X4_T(r0,r1,r2,r3,addr) \
    asm volatile("ldmatrix.sync.aligned.m8n8.x4.trans.shared.b16 {%0,%1,%2,%3}, [%4];" \
        : "=r"(r0), "=r"(r1), "=r"(r2), "=r"(r3) : "r"(addr))
#define MMA16816(c0,c1,c2,c3,a0,a1,a2,a3,b0,b1) \
    asm volatile("mma.sync.aligned.m16n8k16.row.col.f32.f16.f16.f32 " \
        "{%0,%1,%2,%3}, {%4,%5,%6,%7}, {%8,%9}, {%0,%1,%2,%3};" \
        : "+f"(c0), "+f"(c1), "+f"(c2), "+f"(c3) \
        : "r"(a0), "r"(a1), "r"(a2), "r"(a3), "r"(b0), "r"(b1))
#define CP_ASYNC16(smem, gptr) \
    asm volatile("cp.async.cg.shared.global [%0], [%1], 16;" :: "r"(smem), "l"(gptr))
#define CP_COMMIT() asm volatile("cp.async.commit_group;" ::: "memory")
#define CP_WAIT(n)  asm volatile("cp.async.wait_group %0;" :: "n"(n) : "memory")

// ---------------- prep: W^T cvt (z<4) + mask scan (z==4) + x cvt (z==5) ----------------
__global__ void prep_kernel(const float* __restrict__ Wq, const float* __restrict__ Wk,
                            const float* __restrict__ Wv, const float* __restrict__ Wo,
                            const int* __restrict__ mask, const float* __restrict__ x) {
    const int z = blockIdx.z;
    const int tid = threadIdx.y * 32 + threadIdx.x;
    if (z == 5) {            // x fp32 -> fp16
        int bid = blockIdx.y * 32 + blockIdx.x;
        const float4* xs = (const float4*)x;
        uint2* xd = (uint2*)g_xb;
        #pragma unroll
        for (int u = 0; u < 16; u++) {
            int idx = bid*4096 + u*256 + tid;
            float4 a = xs[idx];
            __half2 h0 = __float22half2_rn(make_float2(a.x, a.y));
            __half2 h1 = __float22half2_rn(make_float2(a.z, a.w));
            xd[idx] = make_uint2(*(uint32_t*)&h0, *(uint32_t*)&h1);
        }
        return;
    }
    if (z == 4) {            // mask scan (+ work-counter reset)
        if (blockIdx.y != 0 || blockIdx.x >= BB) return;
        int b = blockIdx.x;
        if (b == 0 && tid == 0) g_work = 0;
        __shared__ int smin, smax;
        if (tid == 0) { smin = NN; smax = -1; }
        __syncthreads();
        int lmin = NN, lmax = -1;
        for (int i = tid; i < NN; i += 256) {
            if (mask[b*NN + i]) { lmin = min(lmin, i); lmax = max(lmax, i); }
        }
        atomicMin(&smin, lmin);
        atomicMax(&smax, lmax);
        __syncthreads();
        if (tid == 0) { g_start[b] = smin; g_end[b] = smax; }
        return;
    }
    if (blockIdx.x >= 8) return;
    __shared__ float t[32][33];
    const float* W = z == 0 ? Wq : z == 1 ? Wk : z == 2 ? Wv : Wo;
    __half* wt = g_wt + (size_t)z * (DM_*DIN_);
    int n0 = blockIdx.x * 32, k0 = blockIdx.y * 32;
    for (int i = threadIdx.y; i < 32; i += 8)
        t[i][threadIdx.x] = W[(size_t)(k0 + i)*DM_ + n0 + threadIdx.x];
    __syncthreads();
    for (int i = threadIdx.y; i < 32; i += 8)
        wt[(size_t)(n0 + i)*DIN_ + k0 + threadIdx.x] = __float2half_rn(t[threadIdx.x][i]);
}

// ---------------- fused QKV GEMM + V-partials + LPT sorter ----------------
#define GST 72
#define GTB ((uint32_t)(64*GST*2))

__device__ __forceinline__ void gemm_prefetch_b(uint32_t dstb, const __half* wp, int tid) {
    #pragma unroll
    for (int u = 0; u < 4; u++) {
        int i = tid + u*128;
        int r = i >> 3, j = i & 7;
        CP_ASYNC16(dstb + (uint32_t)((r*GST + j*8)*2), wp + (size_t)r*DIN_ + j*8);
    }
}

__global__ void __launch_bounds__(128) qkv_hmma_kernel(const float* __restrict__ bq,
                                                       const float* __restrict__ bk,
                                                       const float* __restrict__ bv)
{
    extern __shared__ __align__(16) unsigned char dynsm[];
    const uint32_t sab = smem_u32(dynsm);
    const uint32_t sbb = sab + 4*GTB;

    const int tid = threadIdx.x, lane = tid & 31, warp = tid >> 5;
    const int m0 = blockIdx.y * 64;
    const int h  = blockIdx.x;

    // LPT sorter (one thread of one CTA; prep has already filled g_start/g_end)
    if (blockIdx.x == 0 && blockIdx.y == 0 && tid == 0) {
        int lens[BB], ord[BB];
        for (int b = 0; b < BB; b++) {
            lens[b] = g_end[b] - (g_start[b] & ~63);
            ord[b] = b;
        }
        for (int i = 0; i < BB; i++)
            for (int j = i + 1; j < BB; j++)
                if (lens[ord[j]] > lens[ord[i]]) { int t = ord[i]; ord[i] = ord[j]; ord[j] = t; }
        int p = 0;
        for (int r = 0; r < BB; r++)
            for (int hh = 0; hh < NH_; hh++)
                for (int qt = 0; qt < 16; qt++)
                    g_order[p++] = (short)((((ord[r]*NH_ + hh) << 4)) | qt);
    }

    {
        const __half* xp = g_xb + (size_t)m0*DIN_;
        #pragma unroll
        for (int u = 0; u < 16; u++) {
            int i = tid + u*128;
            int r = i >> 5, j8 = i & 31;
            int t = j8 >> 3, jj = j8 & 7;
            CP_ASYNC16(sab + (uint32_t)(t*GTB) + (uint32_t)((r*GST + jj*8)*2),
                       xp + (size_t)r*DIN_ + j8*8);
        }
        CP_COMMIT();
    }
    gemm_prefetch_b(sbb, g_wt + (size_t)(h*64)*DIN_, tid);
    CP_COMMIT();
    gemm_prefetch_b(sbb + GTB, g_wt + (size_t)(h*64)*DIN_ + 64, tid);
    CP_COMMIT();

    const uint32_t afo = (uint32_t)(((warp*16 + (lane & 15))*GST + (lane >> 4)*8) * 2);
    const uint32_t bfo = (uint32_t)(((((lane & 7) + ((lane >> 4) << 3))*GST) + ((lane >> 3) & 1)*8) * 2);

    float acc[32];
    #pragma unroll
    for (int i = 0; i < 32; i++) acc[i] = 0.f;

    for (int t = 0; t < 12; t++) {
        const int z = t >> 2, k0 = t & 3;
        CP_WAIT(1);
        __syncthreads();
        {
            int tn = t + 2;
            if (tn < 12) {
                int zn = tn >> 2, kn = tn & 3;
                int stn = tn % 3;
                gemm_prefetch_b(sbb + (uint32_t)(stn*GTB),
                                g_wt + (size_t)zn*(DM_*DIN_) + (size_t)(h*64)*DIN_ + kn*64, tid);
            }
            CP_COMMIT();
        }

        uint32_t af[4][4];
        const uint32_t afb = sab + (uint32_t)(k0*GTB) + afo;
        #pragma unroll
        for (int ks = 0; ks < 4; ks++)
            LDSM_X4(af[ks][0], af[ks][1], af[ks][2], af[ks][3], afb + ks*32);

        const uint32_t bfb = sbb + (uint32_t)((t % 3)*GTB) + bfo;
        #pragma unroll
        for (int ks = 0; ks < 4; ks++) {
            #pragma unroll
            for (int ntp = 0; ntp < 4; ntp++) {
                uint32_t b0, b1, b2, b3;
                LDSM_X4(b0, b1, b2, b3, bfb + (uint32_t)((ntp*16*GST + ks*16) * 2));
                MMA16816(acc[(2*ntp)*4+0], acc[(2*ntp)*4+1], acc[(2*ntp)*4+2], acc[(2*ntp)*4+3],
                         af[ks][0], af[ks][1], af[ks][2], af[ks][3], b0, b1);
                MMA16816(acc[(2*ntp+1)*4+0], acc[(2*ntp+1)*4+1], acc[(2*ntp+1)*4+2], acc[(2*ntp+1)*4+3],
                         af[ks][0], af[ks][1], af[ks][2], af[ks][3], b2, b3);
            }
        }

        if (k0 == 3) {
            const float* bias = z == 0 ? bq : z == 1 ? bk : bv;
            __half* dst = z == 0 ? g_qb : z == 1 ? g_kb : g_vb;
            const float os = z == 0 ? SCL2E : 1.f;
            const int r_lo = m0 + warp*16 + (lane >> 2);
            const int r_hi = r_lo + 8;
            const int b_lo = r_lo >> 11, n_lo = r_lo & (NN - 1);
            const int b_hi = r_hi >> 11, n_hi = r_hi & (NN - 1);
            __half* p_lo = dst + ((((size_t)b_lo*NH_ + h)*NN) + n_lo)*DK_;
            __half* p_hi = dst + ((((size_t)b_hi*NH_ + h)*NN) + n_hi)*DK_;
            float cs[16];
            #pragma unroll
            for (int j = 0; j < 8; j++) {
                int d = j*8 + (lane & 3)*2;
                float2 bv2 = *(const float2*)&bias[h*64 + d];
                __half2 lo = __float22half2_rn(make_float2((acc[4*j+0] + bv2.x)*os,
                                                           (acc[4*j+1] + bv2.y)*os));
                __half2 hi = __float22half2_rn(make_float2((acc[4*j+2] + bv2.x)*os,
                                                           (acc[4*j+3] + bv2.y)*os));
                *(uint32_t*)&p_lo[d] = *(uint32_t*)&lo;
                *(uint32_t*)&p_hi[d] = *(uint32_t*)&hi;
                if (z == 2) {   // V: accumulate fp16-rounded column sums over this thread's 2 rows
                    float2 flo = __half22float2(lo);
                    float2 fhi = __half22float2(hi);
                    cs[2*j]   = flo.x + fhi.x;
                    cs[2*j+1] = flo.y + fhi.y;
                }
            }
            if (z == 2) {       // reduce 16 rows within warp (over lane>>2), then 4 warps via smem
                #pragma unroll
                for (int m = 4; m <= 16; m <<= 1)
                    #pragma unroll
                    for (int j = 0; j < 16; j++)
                        cs[j] += __shfl_xor_sync(0xffffffffu, cs[j], m);
                __syncthreads();                    // all smem MMA/LDSM reads done (t==11)
                float* red = (float*)dynsm;         // scratch: 4 warps x 64 cols
                if (lane < 4) {
                    #pragma unroll
                    for (int j = 0; j < 8; j++) {
                        red[warp*64 + j*8 + lane*2]     = cs[2*j];
                        red[warp*64 + j*8 + lane*2 + 1] = cs[2*j+1];
                    }
                }
                __syncthreads();
                if (tid < 64) {
                    float s = red[tid] + red[64 + tid] + red[128 + tid] + red[192 + tid];
                    int bb = m0 >> 11, slot = (m0 & (NN - 1)) >> 6;
                    g_vpart[(((size_t)(bb*NH_ + h))*32 + slot)*DK_ + tid] = s;
                }
            }
            #pragma unroll
            for (int i = 0; i < 32; i++) acc[i] = 0.f;
        }
    }
}

// ---------------- HMMA fp16 flash attention: persistent CTAs, LPT, f16x2 softmax ----------------
#define KST 72
#define QB  ((uint32_t)(128*KST*2))
#define KVB ((uint32_t)(64*KST*2))

__device__ __forceinline__ void attn_prefetch(uint32_t skb, uint32_t svb,
                                              const __half* kp, const __half* vp,
                                              int kb, int tid) {
    #pragma unroll
    for (int u = 0; u < 2; u++) {
        int i = tid + u*256;
        int r = i >> 3, j = i & 7;
        int gr = kb + r; if (gr > NN - 1) gr = NN - 1;
        uint32_t so = (uint32_t)((r*KST + j*8) * 2);
        CP_ASYNC16(skb + so, kp + (size_t)gr*DK_ + j*8);
        CP_ASYNC16(svb + so, vp + (size_t)gr*DK_ + j*8);
    }
}

__global__ void __launch_bounds__(256) attn_mma_kernel() {
    extern __shared__ __align__(16) unsigned char dynsm[];
    __shared__ float vmS[64];
    __shared__ int sIdx;
    __half* sQ = (__half*)dynsm;
    const uint32_t smb = smem_u32(dynsm);
    const uint32_t skb0 = smb + QB;
    const uint32_t svb0 = smb + QB + 3*KVB;

    const int tid = threadIdx.x, lane = tid & 31, warp = tid >> 5;
    const uint32_t kfo = (uint32_t)(((((lane & 7) + ((lane >> 4) << 3))*KST) + ((lane >> 3) & 1)*8) * 2);
    const uint32_t vfo = (uint32_t)(((((lane & 7) + (((lane >> 3) & 1) << 3))*KST) + (lane >> 4)*8) * 2);

    for (;;) {
        if (tid == 0) sIdx = atomicAdd(&g_work, 1);
        __syncthreads();               // broadcast idx; fences smem reuse from prev tile
        const int idx = sIdx;
        if (idx >= NTILES) break;
        const int tile = g_order[idx];
        const int qt = tile & 15, bh = tile >> 4;
        const int b = bh >> 2, h = bh & 3;
        const int q0 = qt * 128;
        const int kstart = g_start[b], kend = g_end[b];
        __half* outbase = g_att + ((size_t)b*NN + q0)*DM_ + h*DK_;

        // lazy vmean fold: only tiles containing invalid query rows need it
        const bool needvm = (q0 < kstart) || (q0 + 127 >= kend);
        if (needvm && tid < 64) {
            float s = 0.f;
            #pragma unroll 8
            for (int seg = 0; seg < 32; seg++)
                s += g_vpart[((size_t)bh*32 + seg)*DK_ + tid];
            vmS[tid] = s * (1.f/NN);
        }
        __syncthreads();

        const bool any = (q0 < kend) && (q0 + 127 >= kstart);
        if (!any) {
            int r = tid >> 1, c0 = (tid & 1) * 32;
            #pragma unroll
            for (int j = 0; j < 8; j++) {
                __half2 a = __float22half2_rn(make_float2(vmS[c0+j*4],   vmS[c0+j*4+1]));
                __half2 c = __float22half2_rn(make_float2(vmS[c0+j*4+2], vmS[c0+j*4+3]));
                *(uint2*)&outbase[(size_t)r*DM_ + c0 + j*4] =
                    make_uint2(*(uint32_t*)&a, *(uint32_t*)&c);
            }
            continue;
        }

        const __half* qp = g_qb + ((size_t)bh*NN + q0)*DK_;
        const __half* kp = g_kb + (size_t)bh*NN*DK_;
        const __half* vp = g_vb + (size_t)bh*NN*DK_;
        const int kb0 = kstart & ~63;

        attn_prefetch(skb0, svb0, kp, vp, kb0, tid);
        CP_COMMIT();
        if (kb0 + 64 < kend)
            attn_prefetch(skb0 + KVB, svb0 + KVB, kp, vp, kb0 + 64, tid);
        CP_COMMIT();

        for (int i = tid; i < 1024; i += 256) {
            int r = i >> 3, j = i & 7;
            *(uint4*)&sQ[r*KST + j*8] = *(const uint4*)&qp[(size_t)r*DK_ + j*8];
        }
        __syncthreads();

        uint32_t qa[4][4];
        {
            uint32_t qaddr = smb + (uint32_t)(((warp*16 + (lane & 15))*KST + (lane >> 4)*8) * 2);
            #pragma unroll
            for (int ks = 0; ks < 4; ks++)
                LDSM_X4(qa[ks][0], qa[ks][1], qa[ks][2], qa[ks][3], qaddr + ks*32);
        }

        float oacc[32];
        #pragma unroll
        for (int i = 0; i < 32; i++) oacc[i] = 0.f;
        float l_lo = 0.f, l_hi = 0.f;
        int st = 0;

        for (int kb = kb0; kb < kend; kb += 64) {
            CP_WAIT(1);
            __syncthreads();

            {
                int stn = st + 2; if (stn >= 3) stn -= 3;
                if (kb + 128 < kend)
                    attn_prefetch(skb0 + stn*KVB, svb0 + stn*KVB, kp, vp, kb + 128, tid);
                CP_COMMIT();
            }

            const uint32_t kfbase = skb0 + st*KVB + kfo;
            const uint32_t vfbase = svb0 + st*KVB + vfo;

            float sacc[32];
            #pragma unroll
            for (int i = 0; i < 32; i++) sacc[i] = 0.f;
            #pragma unroll
            for (int ks = 0; ks < 4; ks++) {
                #pragma unroll
                for (int ntp = 0; ntp < 4; ntp++) {
                    uint32_t b0, b1, b2, b3;
                    LDSM_X4(b0, b1, b2, b3, kfbase + (uint32_t)((ntp*16*KST + ks*16) * 2));
                    MMA16816(sacc[(2*ntp)*4+0], sacc[(2*ntp)*4+1], sacc[(2*ntp)*4+2], sacc[(2*ntp)*4+3],
                             qa[ks][0], qa[ks][1], qa[ks][2], qa[ks][3], b0, b1);
                    MMA16816(sacc[(2*ntp+1)*4+0], sacc[(2*ntp+1)*4+1], sacc[(2*ntp+1)*4+2], sacc[(2*ntp+1)*4+3],
                             qa[ks][0], qa[ks][1], qa[ks][2], qa[ks][3], b2, b3);
                }
            }

            // ---- softmax via ex2.approx.f16x2 (packed, half the MUFU ops) ----
            const bool partial = (kb < kstart) || (kb + 64 > kend);
            uint32_t ppack[16];
            float ls_lo = 0.f, ls_hi = 0.f;
            #pragma unroll
            for (int j = 0; j < 8; j++) {
                __half2 s_lo = __float22half2_rn(make_float2(sacc[4*j+0], sacc[4*j+1]));
                __half2 s_hi = __float22half2_rn(make_float2(sacc[4*j+2], sacc[4*j+3]));
                uint32_t plo = ex2_h2(*(uint32_t*)&s_lo);
                uint32_t phi = ex2_h2(*(uint32_t*)&s_hi);
                if (partial) {
                    int col = kb + j*8 + (lane & 3)*2;
                    uint32_t m = (((col >= kstart) & (col < kend)) ? 0x0000FFFFu : 0u)
                               | (((col + 1 >= kstart) & (col + 1 < kend)) ? 0xFFFF0000u : 0u);
                    plo &= m; phi &= m;
                }
                ppack[2*j]   = plo;
                ppack[2*j+1] = phi;
                float2 f0 = __half22float2(*(__half2*)&plo);
                float2 f1 = __half22float2(*(__half2*)&phi);
                ls_lo += f0.x + f0.y;
                ls_hi += f1.x + f1.y;
            }
            ls_lo += __shfl_xor_sync(0xffffffffu, ls_lo, 1);
            ls_lo += __shfl_xor_sync(0xffffffffu, ls_lo, 2);
            ls_hi += __shfl_xor_sync(0xffffffffu, ls_hi, 1);
            ls_hi += __shfl_xor_sync(0xffffffffu, ls_hi, 2);
            l_lo += ls_lo;
            l_hi += ls_hi;

            #pragma unroll
            for (int kk = 0; kk < 4; kk++) {
                #pragma unroll
                for (int dt = 0; dt < 4; dt++) {
                    uint32_t b0, b1, b2, b3;
                    LDSM_X4_T(b0, b1, b2, b3, vfbase + (uint32_t)((kk*16*KST + dt*16) * 2));
                    MMA16816(oacc[(2*dt)*4+0], oacc[(2*dt)*4+1], oacc[(2*dt)*4+2], oacc[(2*dt)*4+3],
                             ppack[4*kk+0], ppack[4*kk+1], ppack[4*kk+2], ppack[4*kk+3], b0, b1);
                    MMA16816(oacc[(2*dt+1)*4+0], oacc[(2*dt+1)*4+1], oacc[(2*dt+1)*4+2], oacc[(2*dt+1)*4+3],
                             ppack[4*kk+0], ppack[4*kk+1], ppack[4*kk+2], ppack[4*kk+3], b2, b3);
                }
            }
            st = (st + 1 == 3) ? 0 : st + 1;
        }

        const int r_lo = q0 + warp*16 + (lane >> 2);
        const int r_hi = r_lo + 8;
        const bool v_lo = (r_lo >= kstart) && (r_lo < kend);
        const bool v_hi = (r_hi >= kstart) && (r_hi < kend);
        const float inv_lo = v_lo ? 1.f / l_lo : 0.f;
        const float inv_hi = v_hi ? 1.f / l_hi : 0.f;
        __half* orow_lo = g_att + ((size_t)b*NN + r_lo)*DM_ + h*DK_;
        __half* orow_hi = g_att + ((size_t)b*NN + r_hi)*DM_ + h*DK_;
        #pragma unroll
        for (int j = 0; j < 8; j++) {
            int d = j*8 + (lane & 3)*2;
            float2 lo, hi;
            if (v_lo) { lo.x = oacc[4*j+0]*inv_lo; lo.y = oacc[4*j+1]*inv_lo; }
            else      { lo.x = vmS[d]; lo.y = vmS[d+1]; }
            if (v_hi) { hi.x = oacc[4*j+2]*inv_hi; hi.y = oacc[4*j+3]*inv_hi; }
            else      { hi.x = vmS[d]; hi.y = vmS[d+1]; }
            __half2 lo2 = __float22half2_rn(lo);
            __half2 hi2 = __float22half2_rn(hi);
            *(uint32_t*)&orow_lo[d] = *(uint32_t*)&lo2;
            *(uint32_t*)&orow_hi[d] = *(uint32_t*)&hi2;
        }
    }
}

// ---------------- output GEMM, fp16 HMMA, full cp.async, 3-stage B ----------------
__global__ void __launch_bounds__(128) out_hmma_kernel(const float* __restrict__ bo,
                                                       float* __restrict__ out)
{
    extern __shared__ __align__(16) unsigned char dynsm[];
    const uint32_t sab = smem_u32(dynsm);
    const uint32_t sbb = sab + 4*GTB;

    const int tid = threadIdx.x, lane = tid & 31, warp = tid >> 5;
    const int m0 = blockIdx.y * 64;
    const int h  = blockIdx.x;
    const __half* wt = g_wt + (size_t)3 * (DM_*DIN_) + (size_t)(h*64)*DIN_;

    {
        const __half* ap = g_att + (size_t)m0*DM_;
        #pragma unroll
        for (int u = 0; u < 16; u++) {
            int i = tid + u*128;
            int r = i >> 5, j8 = i & 31;
            int t = j8 >> 3, jj = j8 & 7;
            CP_ASYNC16(sab + (uint32_t)(t*GTB) + (uint32_t)((r*GST + jj*8)*2),
                       ap + (size_t)r*DM_ + j8*8);
        }
        CP_COMMIT();
    }
    gemm_prefetch_b(sbb, wt, tid);
    CP_COMMIT();
    gemm_prefetch_b(sbb + GTB, wt + 64, tid);
    CP_COMMIT();

    const uint32_t afo = (uint32_t)(((warp*16 + (lane & 15))*GST + (lane >> 4)*8) * 2);
    const uint32_t bfo = (uint32_t)(((((lane & 7) + ((lane >> 4) << 3))*GST) + ((lane >> 3) & 1)*8) * 2);

    float acc[32];
    #pragma unroll
    for (int i = 0; i < 32; i++) acc[i] = 0.f;

    for (int t = 0; t < 4; t++) {
        CP_WAIT(1);
        __syncthreads();
        {
            int tn = t + 2;
            if (tn < 4)
                gemm_prefetch_b(sbb + (uint32_t)((tn % 3)*GTB), wt + tn*64, tid);
            CP_COMMIT();
        }

        uint32_t af[4][4];
        const uint32_t afb = sab + (uint32_t)(t*GTB) + afo;
        #pragma unroll
        for (int ks = 0; ks < 4; ks++)
            LDSM_X4(af[ks][0], af[ks][1], af[ks][2], af[ks][3], afb + ks*32);

        const uint32_t bfb = sbb + (uint32_t)((t % 3)*GTB) + bfo;
        #pragma unroll
        for (int ks = 0; ks < 4; ks++) {
            #pragma unroll
            for (int ntp = 0; ntp < 4; ntp++) {
                uint32_t b0, b1, b2, b3;
                LDSM_X4(b0, b1, b2, b3, bfb + (uint32_t)((ntp*16*GST + ks*16) * 2));
                MMA16816(acc[(2*ntp)*4+0], acc[(2*ntp)*4+1], acc[(2*ntp)*4+2], acc[(2*ntp)*4+3],
                         af[ks][0], af[ks][1], af[ks][2], af[ks][3], b0, b1);
                MMA16816(acc[(2*ntp+1)*4+0], acc[(2*ntp+1)*4+1], acc[(2*ntp+1)*4+2], acc[(2*ntp+1)*4+3],
                         af[ks][0], af[ks][1], af[ks][2], af[ks][3], b2, b3);
            }
        }
    }

    const int r_lo = m0 + warp*16 + (lane >> 2);
    const int r_hi = r_lo + 8;
    #pragma unroll
    for (int j = 0; j < 8; j++) {
        int d = j*8 + (lane & 3)*2;
        float2 bv2 = *(const float2*)&bo[h*64 + d];
        float2 lo = make_float2(acc[4*j+0] + bv2.x, acc[4*j+1] + bv2.y);
        float2 hi = make_float2(acc[4*j+2] + bv2.x, acc[4*j+3] + bv2.y);
        *(float2*)&out[(size_t)r_lo*DM_ + h*64 + d] = lo;
        *(float2*)&out[(size_t)r_hi*DM_ + h*64 + d] = hi;
    }
}

// ---------------- launch ----------------
extern "C" void kernel_launch(void* const* d_in, const int* in_sizes, int n_in,
                              void* d_out, int out_size) {
    const float* x    = (const float*)d_in[0];
    const int*   mask = (const int*)  d_in[1];
    const float* Wq = (const float*)d_in[2]; const float* bq = (const float*)d_in[3];
    const float* Wk = (const float*)d_in[4]; const float* bk = (const float*)d_in[5];
    const float* Wv = (const float*)d_in[6]; const float* bv = (const float*)d_in[7];
    const float* Wo = (const float*)d_in[8]; const float* bo = (const float*)d_in[9];
    float* out = (float*)d_out;

    const int gemm_smem = 4*9216 + 3*9216;            // 64512
    const int attn_smem = 128*KST*2 + 6*64*KST*2;     // 73728
    cudaFuncSetAttribute(qkv_hmma_kernel, cudaFuncAttributeMaxDynamicSharedMemorySize, gemm_smem);
    cudaFuncSetAttribute(out_hmma_kernel, cudaFuncAttributeMaxDynamicSharedMemorySize, gemm_smem);
    cudaFuncSetAttribute(attn_mma_kernel, cudaFuncAttributeMaxDynamicSharedMemorySize, attn_smem);

    prep_kernel<<<dim3(32, 8, 6), dim3(32, 8)>>>(Wq, Wk, Wv, Wo, mask, x);
    qkv_hmma_kernel<<<dim3(DM_/64, ROWS/64), 128, gemm_smem>>>(bq, bk, bv);
    attn_mma_kernel<<<PERSIST, 256, attn_smem>>>();
    out_hmma_kernel<<<dim3(DM_/64, ROWS/64), 128, gemm_smem>>>(bo, out);
}